// round 12
// baseline (speedup 1.0000x reference)
#include <cuda_runtime.h>
#include <cstdint>
#include <cstddef>

#define BN 16
#define HH 512
#define WW 512
#define NPIX (BN*HH*WW)          // 4194304
#define CNUM 6
#define LNUM 3
#define NTILE 2048               // 4x512 row-band tiles, 128 per sample

// ---------------- static device scratch (no allocations allowed) ----------------
__device__ float    g_img[NPIX];                     // ping image A (build writes here)
__device__ float    g_im2[NPIX];                     // pong image B
__device__ unsigned g_list[(size_t)CNUM * NPIX];     // per-class lists (interior + ring ranges)
__device__ unsigned g_cnt[CNUM];
__device__ unsigned g_toff[CNUM * NTILE];            // interior CSR offset
__device__ unsigned g_tcnt[CNUM * NTILE];            // interior CSR count
__device__ unsigned g_rtoff[CNUM * NTILE];           // ring CSR offset
__device__ unsigned g_rtcnt[CNUM * NTILE];           // ring CSR count
__device__ unsigned g_mnu[BN], g_mxu[BN];            // order-encoded min/max bits
__device__ float    g_tbl[BN * CNUM * 128];          // per (b,cls): 25*float4 weights,
                                                     // float4 biases, 3*float4 bezier params

// ---------------- helpers ----------------
__device__ __forceinline__ unsigned fenc(float f) {
    unsigned b = __float_as_uint(f);
    return (b & 0x80000000u) ? ~b : (b | 0x80000000u);
}
__device__ __forceinline__ float fdec(unsigned u) {
    unsigned b = (u & 0x80000000u) ? (u ^ 0x80000000u) : ~u;
    return __uint_as_float(b);
}
__device__ __forceinline__ float sigm(float x) { return 1.0f / (1.0f + __expf(-x)); }

__device__ __forceinline__ float bez(float c, float mix,
                                     float p1, float p2, float p1v, float p2v) {
    float om  = 1.0f - c;
    float om2 = om * om, c2 = c * c;
    float ct = 3.0f * om2 * c * p1 + 3.0f * om * c2 * p2 + c2 * c;
    float cv = om2 * om + 3.0f * om2 * c * p1v + 3.0f * om * c2 * p2v;
    float v  = ct * mix + cv * (1.0f - mix);
    return fminf(fmaxf(v, 0.0f), 1.0f);
}

// ---------------- setup: counters/minmax init + effective 5x5 table ----------------
__global__ void k_setup(const int* __restrict__ index, const float* __restrict__ param,
                        const float* __restrict__ w1, const float* __restrict__ b1,
                        const float* __restrict__ w2, const float* __restrict__ b2) {
    int t = threadIdx.x;
    if (t < CNUM) g_cnt[t] = 0u;
    if (t < BN) { g_mnu[t] = 0xFFFFFFFFu; g_mxu[t] = 0u; }
    if (t >= BN * CNUM * LNUM) return;
    int b = t / (CNUM * LNUM);
    int i = (t / LNUM) % CNUM;
    int l = t % LNUM;
    int d = __ldg(index + b);
    int k = ((d * CNUM + i) * 4) * LNUM + l;   // aug index fixed to 0
    const float* W1 = w1 + (size_t)k * 36;
    const float* W2 = w2 + (size_t)k * 36;
    const float* B1 = b1 + (size_t)k * 4;
    const float* P  = param + (size_t)k * 7;

    float wef[25];
#pragma unroll
    for (int j = 0; j < 25; j++) wef[j] = 0.0f;
    float beff = __ldg(b2 + k);
#pragma unroll
    for (int ch = 0; ch < 4; ch++) {
        float s2 = 0.0f;
#pragma unroll
        for (int e = 0; e < 9; e++) {
            float w2v = __ldg(W2 + ch * 9 + e);
            s2 += w2v;
            int ey = e / 3, ex = e % 3;
#pragma unroll
            for (int dd = 0; dd < 9; dd++) {
                wef[(ey + dd / 3) * 5 + (ex + dd % 3)] += w2v * __ldg(W1 + ch * 9 + dd);
            }
        }
        beff += __ldg(B1 + ch) * s2;
    }
    float* T = g_tbl + (size_t)(b * CNUM + i) * 128;
#pragma unroll
    for (int j = 0; j < 25; j++) T[j * 4 + l] = wef[j];
    T[100 + l] = beff;
#pragma unroll
    for (int j = 0; j < 4; j++) T[104 + l * 4 + j] = sigm(__ldg(P + j));
    if (l == 0) {
        T[103] = 0.0f;
#pragma unroll
        for (int j = 0; j < 25; j++) T[j * 4 + 3] = 0.0f;
    }
}

// per-sample min/max
__global__ void k_minmax(const float4* __restrict__ x) {
    int b = blockIdx.x >> 3, chunk = blockIdx.x & 7;
    const float4* p = x + (size_t)b * 65536 + (size_t)chunk * 8192;
    float mn = 3.4e38f, mx = -3.4e38f;
    for (int i = threadIdx.x; i < 8192; i += 256) {
        float4 v = __ldg(p + i);
        mn = fminf(mn, fminf(fminf(v.x, v.y), fminf(v.z, v.w)));
        mx = fmaxf(mx, fmaxf(fmaxf(v.x, v.y), fmaxf(v.z, v.w)));
    }
    for (int o = 16; o; o >>= 1) {
        mn = fminf(mn, __shfl_down_sync(0xffffffffu, mn, o));
        mx = fmaxf(mx, __shfl_down_sync(0xffffffffu, mx, o));
    }
    __shared__ float smn[8], smx[8];
    if ((threadIdx.x & 31) == 0) { smn[threadIdx.x >> 5] = mn; smx[threadIdx.x >> 5] = mx; }
    __syncthreads();
    if (threadIdx.x == 0) {
        for (int w = 1; w < 8; w++) { mn = fminf(mn, smn[w]); mx = fmaxf(mx, smx[w]); }
        atomicMin(&g_mnu[b], fenc(mn));
        atomicMax(&g_mxu[b], fenc(mx));
    }
}

// Fused normalize + per-class list build: interior (ballot, sorted) + ring
// (shared-atomic slots) ranges in the same per-class array; two CSRs per tile.
__global__ void __launch_bounds__(256) k_build(const float4* __restrict__ x,
                                               const int* __restrict__ lbl) {
    __shared__ unsigned scur[CNUM];    // interior within-block offsets
    __shared__ unsigned sbase[CNUM];   // interior block base in global list
    __shared__ unsigned srA[CNUM];     // ring counts, then ring cursors
    __shared__ unsigned srbase[CNUM];  // ring block base
    const int t = threadIdx.x;
    const int lane = t & 31;
    const unsigned base = blockIdx.x * 2048u;
    const int b = base >> 18;

    // fused normalization: 2 float4 per thread
    {
        float mn  = fdec(g_mnu[b]);
        float inv = 1.0f / (fdec(g_mxu[b]) - mn + 1e-8f);
        unsigned f4 = (base >> 2) + t;
#pragma unroll
        for (int s = 0; s < 2; s++) {
            float4 v = __ldg(x + f4 + s * 256);
            reinterpret_cast<float4*>(g_img)[f4 + s * 256] =
                make_float4((v.x - mn) * inv, (v.y - mn) * inv,
                            (v.z - mn) * inv, (v.w - mn) * inv);
        }
    }

    if (t < CNUM) { scur[t] = 0u; srA[t] = 0u; }
    __syncthreads();

    // pass A: per-thread interior counts; ring via shared atomics (rare)
    int lc[8];
    unsigned c0 = 0, c1 = 0, c2 = 0, c3 = 0, c4 = 0, c5 = 0;
#pragma unroll
    for (int s = 0; s < 8; s++) {
        unsigned p = base + (unsigned)s * 256u + t;
        int c = __ldg(lbl + p);
        unsigned yy = (p >> 9) & 511u, xx = p & 511u;
        bool ring = !((yy - 1u) < 510u && (xx - 1u) < 510u);
        if (ring) { lc[s] = 8 + c; atomicAdd(&srA[c], 1u); }
        else {
            lc[s] = c;
            c0 += (c == 0); c1 += (c == 1); c2 += (c == 2);
            c3 += (c == 3); c4 += (c == 4); c5 += (c == 5);
        }
    }
#pragma unroll
    for (int o = 16; o; o >>= 1) {
        c0 += __shfl_down_sync(0xffffffffu, c0, o);
        c1 += __shfl_down_sync(0xffffffffu, c1, o);
        c2 += __shfl_down_sync(0xffffffffu, c2, o);
        c3 += __shfl_down_sync(0xffffffffu, c3, o);
        c4 += __shfl_down_sync(0xffffffffu, c4, o);
        c5 += __shfl_down_sync(0xffffffffu, c5, o);
    }
    unsigned w0 = 0, w1o = 0, w2o = 0, w3o = 0, w4o = 0, w5o = 0;
    if (lane == 0) {
        w0  = atomicAdd(&scur[0], c0); w1o = atomicAdd(&scur[1], c1);
        w2o = atomicAdd(&scur[2], c2); w3o = atomicAdd(&scur[3], c3);
        w4o = atomicAdd(&scur[4], c4); w5o = atomicAdd(&scur[5], c5);
    }
    __syncthreads();
    if (t < CNUM) {
        unsigned ci = scur[t], cr = srA[t];
        unsigned gb = atomicAdd(&g_cnt[t], ci + cr);
        sbase[t] = gb;
        g_toff[t * NTILE + blockIdx.x]  = gb;
        g_tcnt[t * NTILE + blockIdx.x]  = ci;
        g_rtoff[t * NTILE + blockIdx.x] = gb + ci;
        g_rtcnt[t * NTILE + blockIdx.x] = cr;
        srbase[t] = gb + ci;
        srA[t] = 0u;                       // reuse as ring emission cursor
    }
    __syncthreads();
    unsigned r0 = sbase[0] + __shfl_sync(0xffffffffu, w0, 0);
    unsigned r1 = sbase[1] + __shfl_sync(0xffffffffu, w1o, 0);
    unsigned r2 = sbase[2] + __shfl_sync(0xffffffffu, w2o, 0);
    unsigned r3 = sbase[3] + __shfl_sync(0xffffffffu, w3o, 0);
    unsigned r4 = sbase[4] + __shfl_sync(0xffffffffu, w4o, 0);
    unsigned r5 = sbase[5] + __shfl_sync(0xffffffffu, w5o, 0);
    const unsigned lmask = (1u << lane) - 1u;

    // pass B: interior atomic-free emit + ring shared-atomic emit
#pragma unroll
    for (int s = 0; s < 8; s++) {
        unsigned p = base + (unsigned)s * 256u + t;
        int myc = lc[s];
        unsigned m;
        m = __ballot_sync(0xffffffffu, myc == 0);
        if (myc == 0) g_list[0 * (size_t)NPIX + r0 + __popc(m & lmask)] = p;
        r0 += __popc(m);
        m = __ballot_sync(0xffffffffu, myc == 1);
        if (myc == 1) g_list[1 * (size_t)NPIX + r1 + __popc(m & lmask)] = p;
        r1 += __popc(m);
        m = __ballot_sync(0xffffffffu, myc == 2);
        if (myc == 2) g_list[2 * (size_t)NPIX + r2 + __popc(m & lmask)] = p;
        r2 += __popc(m);
        m = __ballot_sync(0xffffffffu, myc == 3);
        if (myc == 3) g_list[3 * (size_t)NPIX + r3 + __popc(m & lmask)] = p;
        r3 += __popc(m);
        m = __ballot_sync(0xffffffffu, myc == 4);
        if (myc == 4) g_list[4 * (size_t)NPIX + r4 + __popc(m & lmask)] = p;
        r4 += __popc(m);
        m = __ballot_sync(0xffffffffu, myc == 5);
        if (myc == 5) g_list[5 * (size_t)NPIX + r5 + __popc(m & lmask)] = p;
        r5 += __popc(m);
        if (myc >= 8) {
            int c = myc - 8;
            unsigned slot = atomicAdd(&srA[c], 1u);
            g_list[(size_t)c * NPIX + srbase[c] + slot] = p;
        }
    }
}

// Fused per-class pass: halo -> smem, composed 5x5 for interior list, exact
// two-step conv for ring list, then full coalesced band writeback (ping-pong).
// Eliminates scatter/border kernels and all staging traffic.
__global__ void __launch_bounds__(256) k_fused(int cls, int flip,
        const int* __restrict__ index,
        const float* __restrict__ w1, const float* __restrict__ b1,
        const float* __restrict__ w2, const float* __restrict__ b2) {
    __shared__ float srow[8][516];                 // halo rows y0-2..y0+5, x pad 2
    __shared__ __align__(16) float sres[2048];     // full 4x512 band staging
    __shared__ float4 sW[32];

    const float* src = flip ? g_im2 : g_img;
    float*       dst = flip ? g_img : g_im2;
    const int tile = blockIdx.x;
    const int b  = tile >> 7;
    const int y0 = (tile & 127) << 2;

    // coalesced halo load; rows 2..5 also seed the writeback staging
    const float4* s4 = reinterpret_cast<const float4*>(src) + (size_t)b * 65536;
#pragma unroll
    for (int k = 0; k < 4; k++) {
        int idx = threadIdx.x + k * 256;      // 0..1023
        int r = idx >> 7, xq = idx & 127;
        int y = y0 - 2 + r;
        float4 v = (y >= 0 && y < HH) ? __ldg(s4 + y * 128 + xq)
                                      : make_float4(0.f, 0.f, 0.f, 0.f);
        float* drow = &srow[r][2 + xq * 4];
        drow[0] = v.x; drow[1] = v.y; drow[2] = v.z; drow[3] = v.w;
        if (r >= 2 && r < 6)
            reinterpret_cast<float4*>(sres)[(r - 2) * 128 + xq] = v;
    }
    if (threadIdx.x < 8) {
        srow[threadIdx.x][0] = 0.f;   srow[threadIdx.x][1] = 0.f;
        srow[threadIdx.x][514] = 0.f; srow[threadIdx.x][515] = 0.f;
    }
    if (threadIdx.x < 32)
        sW[threadIdx.x] = __ldg(reinterpret_cast<const float4*>(g_tbl)
                                + (size_t)(b * CNUM + cls) * 32 + threadIdx.x);
    __syncthreads();

    const unsigned* __restrict__ list = g_list + (size_t)cls * NPIX;

    // interior: composed 5x5 x 3 layers
    {
        const unsigned off = g_toff[cls * NTILE + tile];
        const unsigned cnt = g_tcnt[cls * NTILE + tile];
        for (unsigned j = off + threadIdx.x; j < off + cnt; j += 256) {
            unsigned p = __ldg(list + j);
            int lx = (int)(p & 511u) + 2;
            int ly = (int)((p >> 9) & 511u) - y0 + 2;   // 2..5

            float4 bb4 = sW[25];
            float a0 = bb4.x, a1 = bb4.y, a2 = bb4.z;
#pragma unroll
            for (int r = 0; r < 5; r++) {
                const float* row = &srow[ly - 2 + r][lx - 2];
#pragma unroll
                for (int cix = 0; cix < 5; cix++) {
                    float v = row[cix];
                    float4 w = sW[r * 5 + cix];
                    a0 += v * w.x; a1 += v * w.y; a2 += v * w.z;
                }
            }
            float cc = srow[ly][lx];
            float4 pA = sW[26], pB = sW[27], pC = sW[28];
            cc = bez(cc, sigm(a0), pA.x, pA.y, pA.z, pA.w);
            cc = bez(cc, sigm(a1), pB.x, pB.y, pB.z, pB.w);
            cc = bez(cc, sigm(a2), pC.x, pC.y, pC.z, pC.w);
            sres[(ly - 2) * 512 + (lx - 2)] = cc;
        }
    }

    // ring: exact two-step conv (intermediate h zero-padded at image edge),
    // neighborhoods read straight from the zero-padded smem halo
    {
        const unsigned roff = g_rtoff[cls * NTILE + tile];
        const unsigned rcnt = g_rtcnt[cls * NTILE + tile];
        if (rcnt) {
            int d = __ldg(index + b);
            int kb = ((d * CNUM + cls) * 4) * LNUM;
            for (unsigned j = roff + threadIdx.x; j < roff + rcnt; j += 256) {
                unsigned p = __ldg(list + j);
                int x = (int)(p & 511u);
                int y = (int)((p >> 9) & 511u);
                int lx = x + 2, ly = y - y0 + 2;
                float cc = srow[ly][lx];
#pragma unroll
                for (int l = 0; l < LNUM; l++) {
                    int k = kb + l;
                    const float* W1 = w1 + (size_t)k * 36;
                    const float* W2 = w2 + (size_t)k * 36;
                    const float* B1 = b1 + (size_t)k * 4;
                    float acc = __ldg(b2 + k);
#pragma unroll
                    for (int e = 0; e < 9; e++) {
                        int ey = e / 3 - 1, ex = e % 3 - 1;
                        int qy = y + ey, qx = x + ex;
                        if (qy < 0 || qy >= HH || qx < 0 || qx >= WW) continue;
                        float hs = 0.0f;
#pragma unroll
                        for (int ch = 0; ch < 4; ch++) {
                            float h = __ldg(B1 + ch);
#pragma unroll
                            for (int dd = 0; dd < 9; dd++) {
                                h += __ldg(W1 + ch * 9 + dd) *
                                     srow[ly + ey + dd / 3 - 1][lx + ex + dd % 3 - 1];
                            }
                            hs += h * __ldg(W2 + ch * 9 + e);
                        }
                        acc += hs;
                    }
                    float4 pp = sW[26 + l];
                    cc = bez(cc, sigm(acc), pp.x, pp.y, pp.z, pp.w);
                }
                sres[(y - y0) * 512 + x] = cc;
            }
        }
    }

    __syncthreads();

    // full band writeback (coalesced float4): every row written exactly once
    float4* d4 = reinterpret_cast<float4*>(dst) + (size_t)b * 65536 + y0 * 128;
#pragma unroll
    for (int k = 0; k < 2; k++) {
        int i = threadIdx.x + k * 256;
        d4[i] = reinterpret_cast<const float4*>(sres)[i];
    }
}

// denormalize into output (final image lives in g_img after 6 flips)
__global__ void k_final(float4* __restrict__ out) {
    unsigned i = blockIdx.x * 256u + threadIdx.x;
    int b = i >> 16;
    float mn = fdec(g_mnu[b]);
    float sc = fdec(g_mxu[b]) - mn + 1e-8f;
    float4 v = reinterpret_cast<const float4*>(g_img)[i];
    out[i] = make_float4(v.x * sc + mn, v.y * sc + mn, v.z * sc + mn, v.w * sc + mn);
}

// ---------------- launch ----------------
extern "C" void kernel_launch(void* const* d_in, const int* in_sizes, int n_in,
                              void* d_out, int out_size) {
    const float* x     = (const float*)d_in[0];
    const int*   lbl   = (const int*)d_in[1];
    const int*   index = (const int*)d_in[2];
    const float* param = (const float*)d_in[3];
    const float* w1    = (const float*)d_in[4];
    const float* b1    = (const float*)d_in[5];
    const float* w2    = (const float*)d_in[6];
    const float* b2    = (const float*)d_in[7];

    k_setup<<<1, 288>>>(index, param, w1, b1, w2, b2);
    k_minmax<<<BN * 8, 256>>>((const float4*)x);
    k_build<<<NTILE, 256>>>((const float4*)x, lbl);
    for (int c = 0; c < CNUM; c++)
        k_fused<<<NTILE, 256>>>(c, c & 1, index, w1, b1, w2, b2);
    k_final<<<NPIX / 1024, 256>>>((float4*)d_out);
}

// round 13
// speedup vs baseline: 1.6496x; 1.6496x over previous
#include <cuda_runtime.h>
#include <cstdint>
#include <cstddef>

#define BN 16
#define HH 512
#define WW 512
#define NPIX (BN*HH*WW)          // 4194304
#define CNUM 6
#define LNUM 3
#define RINGN 2044               // ring pixels per sample
#define NTILE 2048               // 4x512 row-band tiles, 128 per sample

// ---------------- static device scratch (no allocations allowed) ----------------
__device__ float    g_img[NPIX];                     // ping image A
__device__ float    g_im2[NPIX];                     // pong image B
__device__ unsigned g_list[(size_t)CNUM * NPIX];     // per-class interior pixel lists
__device__ unsigned g_cnt[CNUM];
__device__ unsigned g_toff[CNUM * NTILE];            // CSR: start of (cls,tile)
__device__ unsigned g_tcnt[CNUM * NTILE];            // CSR: count
__device__ unsigned g_mnu[BN], g_mxu[BN];            // order-encoded min/max bits
__device__ float    g_tbl[BN * CNUM * 128];          // per (b,cls): 25*float4 weights,
                                                     // float4 biases, 3*float4 bezier params

// ---------------- helpers ----------------
__device__ __forceinline__ unsigned fenc(float f) {
    unsigned b = __float_as_uint(f);
    return (b & 0x80000000u) ? ~b : (b | 0x80000000u);
}
__device__ __forceinline__ float fdec(unsigned u) {
    unsigned b = (u & 0x80000000u) ? (u ^ 0x80000000u) : ~u;
    return __uint_as_float(b);
}
__device__ __forceinline__ float sigm(float x) { return 1.0f / (1.0f + __expf(-x)); }

__device__ __forceinline__ float bez(float c, float mix,
                                     float p1, float p2, float p1v, float p2v) {
    float om  = 1.0f - c;
    float om2 = om * om, c2 = c * c;
    float ct = 3.0f * om2 * c * p1 + 3.0f * om * c2 * p2 + c2 * c;
    float cv = om2 * om + 3.0f * om2 * c * p1v + 3.0f * om * c2 * p2v;
    float v  = ct * mix + cv * (1.0f - mix);
    return fminf(fmaxf(v, 0.0f), 1.0f);
}

__device__ __forceinline__ void ring_yx(int q, int& y, int& x) {
    if (q < 512)       { y = 0;   x = q; }
    else if (q < 1024) { y = 511; x = q - 512; }
    else if (q < 1534) { x = 0;   y = q - 1023; }
    else               { x = 511; y = q - 1533; }
}

// ---------------- setup: counters/minmax init + effective 5x5 table ----------------
__global__ void k_setup(const int* __restrict__ index, const float* __restrict__ param,
                        const float* __restrict__ w1, const float* __restrict__ b1,
                        const float* __restrict__ w2, const float* __restrict__ b2) {
    int t = threadIdx.x;
    if (t < CNUM) g_cnt[t] = 0u;
    if (t < BN) { g_mnu[t] = 0xFFFFFFFFu; g_mxu[t] = 0u; }
    if (t >= BN * CNUM * LNUM) return;
    int b = t / (CNUM * LNUM);
    int i = (t / LNUM) % CNUM;
    int l = t % LNUM;
    int d = __ldg(index + b);
    int k = ((d * CNUM + i) * 4) * LNUM + l;   // aug index fixed to 0
    const float* W1 = w1 + (size_t)k * 36;
    const float* W2 = w2 + (size_t)k * 36;
    const float* B1 = b1 + (size_t)k * 4;
    const float* P  = param + (size_t)k * 7;

    float wef[25];
#pragma unroll
    for (int j = 0; j < 25; j++) wef[j] = 0.0f;
    float beff = __ldg(b2 + k);
#pragma unroll
    for (int ch = 0; ch < 4; ch++) {
        float s2 = 0.0f;
#pragma unroll
        for (int e = 0; e < 9; e++) {
            float w2v = __ldg(W2 + ch * 9 + e);
            s2 += w2v;
            int ey = e / 3, ex = e % 3;
#pragma unroll
            for (int dd = 0; dd < 9; dd++) {
                wef[(ey + dd / 3) * 5 + (ex + dd % 3)] += w2v * __ldg(W1 + ch * 9 + dd);
            }
        }
        beff += __ldg(B1 + ch) * s2;
    }
    float* T = g_tbl + (size_t)(b * CNUM + i) * 128;
#pragma unroll
    for (int j = 0; j < 25; j++) T[j * 4 + l] = wef[j];
    T[100 + l] = beff;
#pragma unroll
    for (int j = 0; j < 4; j++) T[104 + l * 4 + j] = sigm(__ldg(P + j));
    if (l == 0) {
        T[103] = 0.0f;
#pragma unroll
        for (int j = 0; j < 25; j++) T[j * 4 + 3] = 0.0f;
    }
}

// per-sample min/max
__global__ void k_minmax(const float4* __restrict__ x) {
    int b = blockIdx.x >> 3, chunk = blockIdx.x & 7;
    const float4* p = x + (size_t)b * 65536 + (size_t)chunk * 8192;
    float mn = 3.4e38f, mx = -3.4e38f;
    for (int i = threadIdx.x; i < 8192; i += 256) {
        float4 v = __ldg(p + i);
        mn = fminf(mn, fminf(fminf(v.x, v.y), fminf(v.z, v.w)));
        mx = fmaxf(mx, fmaxf(fmaxf(v.x, v.y), fmaxf(v.z, v.w)));
    }
    for (int o = 16; o; o >>= 1) {
        mn = fminf(mn, __shfl_down_sync(0xffffffffu, mn, o));
        mx = fmaxf(mx, __shfl_down_sync(0xffffffffu, mx, o));
    }
    __shared__ float smn[8], smx[8];
    if ((threadIdx.x & 31) == 0) { smn[threadIdx.x >> 5] = mn; smx[threadIdx.x >> 5] = mx; }
    __syncthreads();
    if (threadIdx.x == 0) {
        for (int w = 1; w < 8; w++) { mn = fminf(mn, smn[w]); mx = fmaxf(mx, smx[w]); }
        atomicMin(&g_mnu[b], fenc(mn));
        atomicMax(&g_mxu[b], fenc(mx));
    }
}

// Fused normalize + per-class INTERIOR list build + per-(class,tile) CSR.
__global__ void __launch_bounds__(256) k_build(const float4* __restrict__ x,
                                               const int* __restrict__ lbl) {
    __shared__ unsigned scur[CNUM];
    __shared__ unsigned sbase[CNUM];
    const int t = threadIdx.x;
    const int lane = t & 31;
    const unsigned base = blockIdx.x * 2048u;
    const int b = base >> 18;

    // fused normalization: 2 float4 per thread
    {
        float mn  = fdec(g_mnu[b]);
        float inv = 1.0f / (fdec(g_mxu[b]) - mn + 1e-8f);
        unsigned f4 = (base >> 2) + t;
#pragma unroll
        for (int s = 0; s < 2; s++) {
            float4 v = __ldg(x + f4 + s * 256);
            reinterpret_cast<float4*>(g_img)[f4 + s * 256] =
                make_float4((v.x - mn) * inv, (v.y - mn) * inv,
                            (v.z - mn) * inv, (v.w - mn) * inv);
        }
    }

    if (t < CNUM) scur[t] = 0u;
    __syncthreads();

    // pass A: counts (interior only), labels stashed
    int lc[8];
    unsigned c0 = 0, c1 = 0, c2 = 0, c3 = 0, c4 = 0, c5 = 0;
#pragma unroll
    for (int s = 0; s < 8; s++) {
        unsigned p = base + (unsigned)s * 256u + t;
        int c = __ldg(lbl + p);
        unsigned yy = (p >> 9) & 511u, xx = p & 511u;
        if (!((yy - 1u) < 510u && (xx - 1u) < 510u)) c = 6;   // ring -> excluded
        lc[s] = c;
        c0 += (c == 0); c1 += (c == 1); c2 += (c == 2);
        c3 += (c == 3); c4 += (c == 4); c5 += (c == 5);
    }
#pragma unroll
    for (int o = 16; o; o >>= 1) {
        c0 += __shfl_down_sync(0xffffffffu, c0, o);
        c1 += __shfl_down_sync(0xffffffffu, c1, o);
        c2 += __shfl_down_sync(0xffffffffu, c2, o);
        c3 += __shfl_down_sync(0xffffffffu, c3, o);
        c4 += __shfl_down_sync(0xffffffffu, c4, o);
        c5 += __shfl_down_sync(0xffffffffu, c5, o);
    }
    unsigned w0 = 0, w1o = 0, w2o = 0, w3o = 0, w4o = 0, w5o = 0;
    if (lane == 0) {
        w0  = atomicAdd(&scur[0], c0); w1o = atomicAdd(&scur[1], c1);
        w2o = atomicAdd(&scur[2], c2); w3o = atomicAdd(&scur[3], c3);
        w4o = atomicAdd(&scur[4], c4); w5o = atomicAdd(&scur[5], c5);
    }
    __syncthreads();
    if (t < CNUM) {
        unsigned tot = scur[t];
        unsigned gb = atomicAdd(&g_cnt[t], tot);
        sbase[t] = gb;
        g_toff[t * NTILE + blockIdx.x] = gb;
        g_tcnt[t * NTILE + blockIdx.x] = tot;
    }
    __syncthreads();
    unsigned r0 = sbase[0] + __shfl_sync(0xffffffffu, w0, 0);
    unsigned r1 = sbase[1] + __shfl_sync(0xffffffffu, w1o, 0);
    unsigned r2 = sbase[2] + __shfl_sync(0xffffffffu, w2o, 0);
    unsigned r3 = sbase[3] + __shfl_sync(0xffffffffu, w3o, 0);
    unsigned r4 = sbase[4] + __shfl_sync(0xffffffffu, w4o, 0);
    unsigned r5 = sbase[5] + __shfl_sync(0xffffffffu, w5o, 0);
    const unsigned lmask = (1u << lane) - 1u;

    // pass B: atomic-free emit
#pragma unroll
    for (int s = 0; s < 8; s++) {
        unsigned p = base + (unsigned)s * 256u + t;
        int myc = lc[s];
        unsigned m;
        m = __ballot_sync(0xffffffffu, myc == 0);
        if (myc == 0) g_list[0 * (size_t)NPIX + r0 + __popc(m & lmask)] = p;
        r0 += __popc(m);
        m = __ballot_sync(0xffffffffu, myc == 1);
        if (myc == 1) g_list[1 * (size_t)NPIX + r1 + __popc(m & lmask)] = p;
        r1 += __popc(m);
        m = __ballot_sync(0xffffffffu, myc == 2);
        if (myc == 2) g_list[2 * (size_t)NPIX + r2 + __popc(m & lmask)] = p;
        r2 += __popc(m);
        m = __ballot_sync(0xffffffffu, myc == 3);
        if (myc == 3) g_list[3 * (size_t)NPIX + r3 + __popc(m & lmask)] = p;
        r3 += __popc(m);
        m = __ballot_sync(0xffffffffu, myc == 4);
        if (myc == 4) g_list[4 * (size_t)NPIX + r4 + __popc(m & lmask)] = p;
        r4 += __popc(m);
        m = __ballot_sync(0xffffffffu, myc == 5);
        if (myc == 5) g_list[5 * (size_t)NPIX + r5 + __popc(m & lmask)] = p;
        r5 += __popc(m);
    }
}

// Slim fused per-class pass (INTERIOR ONLY): halo -> smem, composed 5x5 from LDS,
// coalesced full-band writeback src->dst (ping-pong). No ring path here (keeps
// registers low; ring handled by k_ring afterwards).
__global__ void __launch_bounds__(256) k_fused(int cls, int flip) {
    __shared__ float srow[8][516];                 // halo rows y0-2..y0+5, x pad 2
    __shared__ __align__(16) float sres[2048];     // full 4x512 band staging
    __shared__ float4 sW[32];

    const float* src = flip ? g_im2 : g_img;
    float*       dst = flip ? g_img : g_im2;
    const int tile = blockIdx.x;
    const int b  = tile >> 7;
    const int y0 = (tile & 127) << 2;

    // coalesced halo load; rows 2..5 also seed the writeback staging
    const float4* s4 = reinterpret_cast<const float4*>(src) + (size_t)b * 65536;
#pragma unroll
    for (int k = 0; k < 4; k++) {
        int idx = threadIdx.x + k * 256;      // 0..1023
        int r = idx >> 7, xq = idx & 127;
        int y = y0 - 2 + r;
        float4 v = (y >= 0 && y < HH) ? __ldg(s4 + y * 128 + xq)
                                      : make_float4(0.f, 0.f, 0.f, 0.f);
        float* drow = &srow[r][2 + xq * 4];
        drow[0] = v.x; drow[1] = v.y; drow[2] = v.z; drow[3] = v.w;
        if (r >= 2 && r < 6)
            reinterpret_cast<float4*>(sres)[(r - 2) * 128 + xq] = v;
    }
    if (threadIdx.x < 8) {
        srow[threadIdx.x][0] = 0.f;   srow[threadIdx.x][1] = 0.f;
        srow[threadIdx.x][514] = 0.f; srow[threadIdx.x][515] = 0.f;
    }
    if (threadIdx.x < 32)
        sW[threadIdx.x] = __ldg(reinterpret_cast<const float4*>(g_tbl)
                                + (size_t)(b * CNUM + cls) * 32 + threadIdx.x);
    __syncthreads();

    const unsigned off = g_toff[cls * NTILE + tile];
    const unsigned cnt = g_tcnt[cls * NTILE + tile];
    const unsigned* __restrict__ list = g_list + (size_t)cls * NPIX;
    for (unsigned j = off + threadIdx.x; j < off + cnt; j += 256) {
        unsigned p = __ldg(list + j);
        int lx = (int)(p & 511u) + 2;
        int ly = (int)((p >> 9) & 511u) - y0 + 2;   // 2..5

        float4 bb4 = sW[25];
        float a0 = bb4.x, a1 = bb4.y, a2 = bb4.z;
#pragma unroll
        for (int r = 0; r < 5; r++) {
            const float* row = &srow[ly - 2 + r][lx - 2];
#pragma unroll
            for (int cix = 0; cix < 5; cix++) {
                float v = row[cix];
                float4 w = sW[r * 5 + cix];
                a0 += v * w.x; a1 += v * w.y; a2 += v * w.z;
            }
        }
        float cc = srow[ly][lx];
        float4 pA = sW[26], pB = sW[27], pC = sW[28];
        cc = bez(cc, sigm(a0), pA.x, pA.y, pA.z, pA.w);
        cc = bez(cc, sigm(a1), pB.x, pB.y, pB.z, pB.w);
        cc = bez(cc, sigm(a2), pC.x, pC.y, pC.z, pC.w);
        sres[(ly - 2) * 512 + (lx - 2)] = cc;
    }
    __syncthreads();

    // full band writeback (coalesced float4)
    float4* d4 = reinterpret_cast<float4*>(dst) + (size_t)b * 65536 + y0 * 128;
#pragma unroll
    for (int k = 0; k < 2; k++) {
        int i = threadIdx.x + k * 256;
        d4[i] = reinterpret_cast<const float4*>(sres)[i];
    }
}

// Border ring: exact two-step conv reading src, writing labeled ring pixels of
// dst directly (runs after k_fused; overwrites the stale copies it wrote).
__global__ void k_ring(int cls, int flip, const int* __restrict__ lbl,
                       const int* __restrict__ index,
                       const float* __restrict__ w1, const float* __restrict__ b1,
                       const float* __restrict__ w2, const float* __restrict__ b2) {
    const float* src = flip ? g_im2 : g_img;
    float*       dst = flip ? g_img : g_im2;
    int r = blockIdx.x * 256 + threadIdx.x;
    if (r >= BN * RINGN) return;
    int b = r / RINGN, q = r % RINGN;
    int y, x;
    ring_yx(q, y, x);
    unsigned p = ((unsigned)b << 18) | ((unsigned)y << 9) | (unsigned)x;
    if (__ldg(lbl + p) != cls) return;

    const float* basep = src + ((size_t)b << 18);
    float nb[25];
#pragma unroll
    for (int t = 0; t < 25; t++) {
        int yy = y + t / 5 - 2, xx = x + t % 5 - 2;
        nb[t] = (yy >= 0 && yy < HH && xx >= 0 && xx < WW)
                ? __ldg(basep + yy * WW + xx) : 0.0f;
    }
    float cc = nb[12];
    int d = __ldg(index + b);
    int kb = ((d * CNUM + cls) * 4) * LNUM;
    const float* T = g_tbl + (size_t)(b * CNUM + cls) * 128;
#pragma unroll
    for (int l = 0; l < LNUM; l++) {
        int k = kb + l;
        const float* W1 = w1 + (size_t)k * 36;
        const float* W2 = w2 + (size_t)k * 36;
        const float* B1 = b1 + (size_t)k * 4;
        float acc = __ldg(b2 + k);
#pragma unroll
        for (int e = 0; e < 9; e++) {
            int ey = e / 3 - 1, ex = e % 3 - 1;
            int qy = y + ey, qx = x + ex;
            if (qy < 0 || qy >= HH || qx < 0 || qx >= WW) continue;
            float hs = 0.0f;
#pragma unroll
            for (int ch = 0; ch < 4; ch++) {
                float h = __ldg(B1 + ch);
#pragma unroll
                for (int dd = 0; dd < 9; dd++) {
                    int dy = dd / 3 - 1, dx = dd % 3 - 1;
                    h += __ldg(W1 + ch * 9 + dd) * nb[(2 + ey + dy) * 5 + (2 + ex + dx)];
                }
                hs += h * __ldg(W2 + ch * 9 + e);
            }
            acc += hs;
        }
        cc = bez(cc, sigm(acc), T[104 + l * 4], T[105 + l * 4],
                 T[106 + l * 4], T[107 + l * 4]);
    }
    dst[p] = cc;
}

// denormalize into output (after 6 flips the final image is in g_img)
__global__ void k_final(float4* __restrict__ out) {
    unsigned i = blockIdx.x * 256u + threadIdx.x;
    int b = i >> 16;
    float mn = fdec(g_mnu[b]);
    float sc = fdec(g_mxu[b]) - mn + 1e-8f;
    float4 v = reinterpret_cast<const float4*>(g_img)[i];
    out[i] = make_float4(v.x * sc + mn, v.y * sc + mn, v.z * sc + mn, v.w * sc + mn);
}

// ---------------- launch ----------------
extern "C" void kernel_launch(void* const* d_in, const int* in_sizes, int n_in,
                              void* d_out, int out_size) {
    const float* x     = (const float*)d_in[0];
    const int*   lbl   = (const int*)d_in[1];
    const int*   index = (const int*)d_in[2];
    const float* param = (const float*)d_in[3];
    const float* w1    = (const float*)d_in[4];
    const float* b1    = (const float*)d_in[5];
    const float* w2    = (const float*)d_in[6];
    const float* b2    = (const float*)d_in[7];

    k_setup<<<1, 288>>>(index, param, w1, b1, w2, b2);
    k_minmax<<<BN * 8, 256>>>((const float4*)x);
    k_build<<<NTILE, 256>>>((const float4*)x, lbl);
    const int ringBlocks = (BN * RINGN + 255) / 256;  // 128
    for (int c = 0; c < CNUM; c++) {
        k_fused<<<NTILE, 256>>>(c, c & 1);
        k_ring<<<ringBlocks, 256>>>(c, c & 1, lbl, index, w1, b1, w2, b2);
    }
    k_final<<<NPIX / 1024, 256>>>((float4*)d_out);
}

// round 14
// speedup vs baseline: 1.7643x; 1.0695x over previous
#include <cuda_runtime.h>
#include <cstdint>
#include <cstddef>

#define BN 16
#define HH 512
#define WW 512
#define NPIX (BN*HH*WW)          // 4194304
#define CNUM 6
#define LNUM 3
#define RINGN 2044               // ring pixels per sample
#define NTILE 2048               // build tiles: 4x512 (CSR granularity)
#define FTILE 1024               // fused tiles: 8x512

// ---------------- static device scratch (no allocations allowed) ----------------
__device__ float    g_img[NPIX];                     // ping image A
__device__ float    g_im2[NPIX];                     // pong image B
__device__ unsigned g_list[(size_t)CNUM * NPIX];     // per-class interior pixel lists
__device__ unsigned g_cnt[CNUM];
__device__ unsigned g_toff[CNUM * NTILE];            // CSR: start of (cls,tile)
__device__ unsigned g_tcnt[CNUM * NTILE];            // CSR: count
__device__ unsigned g_mnu[BN], g_mxu[BN];            // order-encoded min/max bits
__device__ float    g_tbl[BN * CNUM * 128];          // per (b,cls): 25*float4 weights,
                                                     // float4 biases, 3*float4 bezier params
__constant__ float4 cTbl[BN * CNUM * 32];            // same table, constant bank (48KB)

// ---------------- helpers ----------------
__device__ __forceinline__ unsigned fenc(float f) {
    unsigned b = __float_as_uint(f);
    return (b & 0x80000000u) ? ~b : (b | 0x80000000u);
}
__device__ __forceinline__ float fdec(unsigned u) {
    unsigned b = (u & 0x80000000u) ? (u ^ 0x80000000u) : ~u;
    return __uint_as_float(b);
}
__device__ __forceinline__ float sigm(float x) { return 1.0f / (1.0f + __expf(-x)); }

__device__ __forceinline__ float bez(float c, float mix,
                                     float p1, float p2, float p1v, float p2v) {
    float om  = 1.0f - c;
    float om2 = om * om, c2 = c * c;
    float ct = 3.0f * om2 * c * p1 + 3.0f * om * c2 * p2 + c2 * c;
    float cv = om2 * om + 3.0f * om2 * c * p1v + 3.0f * om * c2 * p2v;
    float v  = ct * mix + cv * (1.0f - mix);
    return fminf(fmaxf(v, 0.0f), 1.0f);
}

__device__ __forceinline__ void ring_yx(int q, int& y, int& x) {
    if (q < 512)       { y = 0;   x = q; }
    else if (q < 1024) { y = 511; x = q - 512; }
    else if (q < 1534) { x = 0;   y = q - 1023; }
    else               { x = 511; y = q - 1533; }
}

// ---------------- setup: counters/minmax init + effective 5x5 table ----------------
__global__ void k_setup(const int* __restrict__ index, const float* __restrict__ param,
                        const float* __restrict__ w1, const float* __restrict__ b1,
                        const float* __restrict__ w2, const float* __restrict__ b2) {
    int t = threadIdx.x;
    if (t < CNUM) g_cnt[t] = 0u;
    if (t < BN) { g_mnu[t] = 0xFFFFFFFFu; g_mxu[t] = 0u; }
    if (t >= BN * CNUM * LNUM) return;
    int b = t / (CNUM * LNUM);
    int i = (t / LNUM) % CNUM;
    int l = t % LNUM;
    int d = __ldg(index + b);
    int k = ((d * CNUM + i) * 4) * LNUM + l;   // aug index fixed to 0
    const float* W1 = w1 + (size_t)k * 36;
    const float* W2 = w2 + (size_t)k * 36;
    const float* B1 = b1 + (size_t)k * 4;
    const float* P  = param + (size_t)k * 7;

    float wef[25];
#pragma unroll
    for (int j = 0; j < 25; j++) wef[j] = 0.0f;
    float beff = __ldg(b2 + k);
#pragma unroll
    for (int ch = 0; ch < 4; ch++) {
        float s2 = 0.0f;
#pragma unroll
        for (int e = 0; e < 9; e++) {
            float w2v = __ldg(W2 + ch * 9 + e);
            s2 += w2v;
            int ey = e / 3, ex = e % 3;
#pragma unroll
            for (int dd = 0; dd < 9; dd++) {
                wef[(ey + dd / 3) * 5 + (ex + dd % 3)] += w2v * __ldg(W1 + ch * 9 + dd);
            }
        }
        beff += __ldg(B1 + ch) * s2;
    }
    float* T = g_tbl + (size_t)(b * CNUM + i) * 128;
#pragma unroll
    for (int j = 0; j < 25; j++) T[j * 4 + l] = wef[j];
    T[100 + l] = beff;
#pragma unroll
    for (int j = 0; j < 4; j++) T[104 + l * 4 + j] = sigm(__ldg(P + j));
    if (l == 0) {
        T[103] = 0.0f;
#pragma unroll
        for (int j = 0; j < 25; j++) T[j * 4 + 3] = 0.0f;
    }
}

// per-sample min/max
__global__ void k_minmax(const float4* __restrict__ x) {
    int b = blockIdx.x >> 3, chunk = blockIdx.x & 7;
    const float4* p = x + (size_t)b * 65536 + (size_t)chunk * 8192;
    float mn = 3.4e38f, mx = -3.4e38f;
    for (int i = threadIdx.x; i < 8192; i += 256) {
        float4 v = __ldg(p + i);
        mn = fminf(mn, fminf(fminf(v.x, v.y), fminf(v.z, v.w)));
        mx = fmaxf(mx, fmaxf(fmaxf(v.x, v.y), fmaxf(v.z, v.w)));
    }
    for (int o = 16; o; o >>= 1) {
        mn = fminf(mn, __shfl_down_sync(0xffffffffu, mn, o));
        mx = fmaxf(mx, __shfl_down_sync(0xffffffffu, mx, o));
    }
    __shared__ float smn[8], smx[8];
    if ((threadIdx.x & 31) == 0) { smn[threadIdx.x >> 5] = mn; smx[threadIdx.x >> 5] = mx; }
    __syncthreads();
    if (threadIdx.x == 0) {
        for (int w = 1; w < 8; w++) { mn = fminf(mn, smn[w]); mx = fmaxf(mx, smx[w]); }
        atomicMin(&g_mnu[b], fenc(mn));
        atomicMax(&g_mxu[b], fenc(mx));
    }
}

// Fused normalize + per-class INTERIOR list build + per-(class,tile) CSR.
__global__ void __launch_bounds__(256) k_build(const float4* __restrict__ x,
                                               const int* __restrict__ lbl) {
    __shared__ unsigned scur[CNUM];
    __shared__ unsigned sbase[CNUM];
    const int t = threadIdx.x;
    const int lane = t & 31;
    const unsigned base = blockIdx.x * 2048u;
    const int b = base >> 18;

    // fused normalization: 2 float4 per thread
    {
        float mn  = fdec(g_mnu[b]);
        float inv = 1.0f / (fdec(g_mxu[b]) - mn + 1e-8f);
        unsigned f4 = (base >> 2) + t;
#pragma unroll
        for (int s = 0; s < 2; s++) {
            float4 v = __ldg(x + f4 + s * 256);
            reinterpret_cast<float4*>(g_img)[f4 + s * 256] =
                make_float4((v.x - mn) * inv, (v.y - mn) * inv,
                            (v.z - mn) * inv, (v.w - mn) * inv);
        }
    }

    if (t < CNUM) scur[t] = 0u;
    __syncthreads();

    // pass A: counts (interior only), labels stashed
    int lc[8];
    unsigned c0 = 0, c1 = 0, c2 = 0, c3 = 0, c4 = 0, c5 = 0;
#pragma unroll
    for (int s = 0; s < 8; s++) {
        unsigned p = base + (unsigned)s * 256u + t;
        int c = __ldg(lbl + p);
        unsigned yy = (p >> 9) & 511u, xx = p & 511u;
        if (!((yy - 1u) < 510u && (xx - 1u) < 510u)) c = 6;   // ring -> excluded
        lc[s] = c;
        c0 += (c == 0); c1 += (c == 1); c2 += (c == 2);
        c3 += (c == 3); c4 += (c == 4); c5 += (c == 5);
    }
#pragma unroll
    for (int o = 16; o; o >>= 1) {
        c0 += __shfl_down_sync(0xffffffffu, c0, o);
        c1 += __shfl_down_sync(0xffffffffu, c1, o);
        c2 += __shfl_down_sync(0xffffffffu, c2, o);
        c3 += __shfl_down_sync(0xffffffffu, c3, o);
        c4 += __shfl_down_sync(0xffffffffu, c4, o);
        c5 += __shfl_down_sync(0xffffffffu, c5, o);
    }
    unsigned w0 = 0, w1o = 0, w2o = 0, w3o = 0, w4o = 0, w5o = 0;
    if (lane == 0) {
        w0  = atomicAdd(&scur[0], c0); w1o = atomicAdd(&scur[1], c1);
        w2o = atomicAdd(&scur[2], c2); w3o = atomicAdd(&scur[3], c3);
        w4o = atomicAdd(&scur[4], c4); w5o = atomicAdd(&scur[5], c5);
    }
    __syncthreads();
    if (t < CNUM) {
        unsigned tot = scur[t];
        unsigned gb = atomicAdd(&g_cnt[t], tot);
        sbase[t] = gb;
        g_toff[t * NTILE + blockIdx.x] = gb;
        g_tcnt[t * NTILE + blockIdx.x] = tot;
    }
    __syncthreads();
    unsigned r0 = sbase[0] + __shfl_sync(0xffffffffu, w0, 0);
    unsigned r1 = sbase[1] + __shfl_sync(0xffffffffu, w1o, 0);
    unsigned r2 = sbase[2] + __shfl_sync(0xffffffffu, w2o, 0);
    unsigned r3 = sbase[3] + __shfl_sync(0xffffffffu, w3o, 0);
    unsigned r4 = sbase[4] + __shfl_sync(0xffffffffu, w4o, 0);
    unsigned r5 = sbase[5] + __shfl_sync(0xffffffffu, w5o, 0);
    const unsigned lmask = (1u << lane) - 1u;

    // pass B: atomic-free emit
#pragma unroll
    for (int s = 0; s < 8; s++) {
        unsigned p = base + (unsigned)s * 256u + t;
        int myc = lc[s];
        unsigned m;
        m = __ballot_sync(0xffffffffu, myc == 0);
        if (myc == 0) g_list[0 * (size_t)NPIX + r0 + __popc(m & lmask)] = p;
        r0 += __popc(m);
        m = __ballot_sync(0xffffffffu, myc == 1);
        if (myc == 1) g_list[1 * (size_t)NPIX + r1 + __popc(m & lmask)] = p;
        r1 += __popc(m);
        m = __ballot_sync(0xffffffffu, myc == 2);
        if (myc == 2) g_list[2 * (size_t)NPIX + r2 + __popc(m & lmask)] = p;
        r2 += __popc(m);
        m = __ballot_sync(0xffffffffu, myc == 3);
        if (myc == 3) g_list[3 * (size_t)NPIX + r3 + __popc(m & lmask)] = p;
        r3 += __popc(m);
        m = __ballot_sync(0xffffffffu, myc == 4);
        if (myc == 4) g_list[4 * (size_t)NPIX + r4 + __popc(m & lmask)] = p;
        r4 += __popc(m);
        m = __ballot_sync(0xffffffffu, myc == 5);
        if (myc == 5) g_list[5 * (size_t)NPIX + r5 + __popc(m & lmask)] = p;
        r5 += __popc(m);
    }
}

// Slim fused per-class pass (INTERIOR ONLY), 8-row tiles:
//  - 12-row halo -> 16B-aligned smem (zero-padded x/y borders)
//  - band rows seeded straight to dst (STG.128) during the halo load
//  - composed 5x5 x 3 layers; weights/params from __constant__ (off L1tex)
//  - results stored directly to dst (ping-pong buffers; no staging)
__global__ void __launch_bounds__(256, 5) k_fused(int cls, int flip) {
    __shared__ float srow[12][520];    // data at cols [4..515]; zeros [2..3],[516..517]

    const float* src = flip ? g_im2 : g_img;
    float*       dst = flip ? g_img : g_im2;
    const int tile = blockIdx.x;       // 0..1023
    const int b  = tile >> 6;          // 64 bands per sample
    const int y0 = (tile & 63) << 3;

    const float4* s4 = reinterpret_cast<const float4*>(src) + (size_t)b * 65536;
    float4*       d4 = reinterpret_cast<float4*>(dst) + (size_t)b * 65536;

    // halo load (12 rows x 128 float4) + direct band seed to dst
#pragma unroll
    for (int k = 0; k < 6; k++) {
        int idx = threadIdx.x + k * 256;      // 0..1535
        int r = idx >> 7, xq = idx & 127;
        int y = y0 - 2 + r;
        float4 v = (y >= 0 && y < HH) ? __ldg(s4 + y * 128 + xq)
                                      : make_float4(0.f, 0.f, 0.f, 0.f);
        *reinterpret_cast<float4*>(&srow[r][4 + xq * 4]) = v;
        if (r >= 2 && r < 10) d4[y * 128 + xq] = v;
    }
    if (threadIdx.x < 12) {
        srow[threadIdx.x][2] = 0.f;   srow[threadIdx.x][3] = 0.f;
        srow[threadIdx.x][516] = 0.f; srow[threadIdx.x][517] = 0.f;
    }
    __syncthreads();

    const int cb = (b * CNUM + cls) * 32;     // uniform constant index
    const unsigned* __restrict__ list = g_list + (size_t)cls * NPIX;

#pragma unroll
    for (int h = 0; h < 2; h++) {
        const int ct = 2 * tile + h;          // CSR tile (4-row granularity)
        const unsigned off = g_toff[cls * NTILE + ct];
        const unsigned cnt = g_tcnt[cls * NTILE + ct];
        for (unsigned j = off + threadIdx.x; j < off + cnt; j += 256) {
            unsigned p = __ldg(list + j);
            int lx = (int)(p & 511u) + 4;
            int ly = (int)((p >> 9) & 511u) - y0 + 2;   // 2..9

            float4 bb4 = cTbl[cb + 25];
            float a0 = bb4.x, a1 = bb4.y, a2 = bb4.z;
#pragma unroll
            for (int r = 0; r < 5; r++) {
                const float* row = &srow[ly - 2 + r][lx - 2];
#pragma unroll
                for (int cix = 0; cix < 5; cix++) {
                    float v = row[cix];
                    float4 w = cTbl[cb + r * 5 + cix];
                    a0 += v * w.x; a1 += v * w.y; a2 += v * w.z;
                }
            }
            float cc = srow[ly][lx];
            float4 pA = cTbl[cb + 26], pB = cTbl[cb + 27], pC = cTbl[cb + 28];
            cc = bez(cc, sigm(a0), pA.x, pA.y, pA.z, pA.w);
            cc = bez(cc, sigm(a1), pB.x, pB.y, pB.z, pB.w);
            cc = bez(cc, sigm(a2), pC.x, pC.y, pC.z, pC.w);
            dst[p] = cc;                      // overwrites seeded value (post-sync)
        }
    }
}

// Border ring: exact two-step conv reading src, writing labeled ring pixels of
// dst directly (runs after k_fused; overwrites the stale seeded copies).
__global__ void k_ring(int cls, int flip, const int* __restrict__ lbl,
                       const int* __restrict__ index,
                       const float* __restrict__ w1, const float* __restrict__ b1,
                       const float* __restrict__ w2, const float* __restrict__ b2) {
    const float* src = flip ? g_im2 : g_img;
    float*       dst = flip ? g_img : g_im2;
    int r = blockIdx.x * 256 + threadIdx.x;
    if (r >= BN * RINGN) return;
    int b = r / RINGN, q = r % RINGN;
    int y, x;
    ring_yx(q, y, x);
    unsigned p = ((unsigned)b << 18) | ((unsigned)y << 9) | (unsigned)x;
    if (__ldg(lbl + p) != cls) return;

    const float* basep = src + ((size_t)b << 18);
    float nb[25];
#pragma unroll
    for (int t = 0; t < 25; t++) {
        int yy = y + t / 5 - 2, xx = x + t % 5 - 2;
        nb[t] = (yy >= 0 && yy < HH && xx >= 0 && xx < WW)
                ? __ldg(basep + yy * WW + xx) : 0.0f;
    }
    float cc = nb[12];
    int d = __ldg(index + b);
    int kb = ((d * CNUM + cls) * 4) * LNUM;
    const float* T = g_tbl + (size_t)(b * CNUM + cls) * 128;
#pragma unroll
    for (int l = 0; l < LNUM; l++) {
        int k = kb + l;
        const float* W1 = w1 + (size_t)k * 36;
        const float* W2 = w2 + (size_t)k * 36;
        const float* B1 = b1 + (size_t)k * 4;
        float acc = __ldg(b2 + k);
#pragma unroll
        for (int e = 0; e < 9; e++) {
            int ey = e / 3 - 1, ex = e % 3 - 1;
            int qy = y + ey, qx = x + ex;
            if (qy < 0 || qy >= HH || qx < 0 || qx >= WW) continue;
            float hs = 0.0f;
#pragma unroll
            for (int ch = 0; ch < 4; ch++) {
                float h = __ldg(B1 + ch);
#pragma unroll
                for (int dd = 0; dd < 9; dd++) {
                    int dy = dd / 3 - 1, dx = dd % 3 - 1;
                    h += __ldg(W1 + ch * 9 + dd) * nb[(2 + ey + dy) * 5 + (2 + ex + dx)];
                }
                hs += h * __ldg(W2 + ch * 9 + e);
            }
            acc += hs;
        }
        cc = bez(cc, sigm(acc), T[104 + l * 4], T[105 + l * 4],
                 T[106 + l * 4], T[107 + l * 4]);
    }
    dst[p] = cc;
}

// denormalize into output (after 6 flips the final image is in g_img)
__global__ void k_final(float4* __restrict__ out) {
    unsigned i = blockIdx.x * 256u + threadIdx.x;
    int b = i >> 16;
    float mn = fdec(g_mnu[b]);
    float sc = fdec(g_mxu[b]) - mn + 1e-8f;
    float4 v = reinterpret_cast<const float4*>(g_img)[i];
    out[i] = make_float4(v.x * sc + mn, v.y * sc + mn, v.z * sc + mn, v.w * sc + mn);
}

// ---------------- launch ----------------
extern "C" void kernel_launch(void* const* d_in, const int* in_sizes, int n_in,
                              void* d_out, int out_size) {
    const float* x     = (const float*)d_in[0];
    const int*   lbl   = (const int*)d_in[1];
    const int*   index = (const int*)d_in[2];
    const float* param = (const float*)d_in[3];
    const float* w1    = (const float*)d_in[4];
    const float* b1    = (const float*)d_in[5];
    const float* w2    = (const float*)d_in[6];
    const float* b2    = (const float*)d_in[7];

    k_setup<<<1, 288>>>(index, param, w1, b1, w2, b2);

    // copy effective table into the constant bank (graph-capturable D2D memcpy)
    void *cdst = nullptr, *csrc = nullptr;
    cudaGetSymbolAddress(&cdst, cTbl);
    cudaGetSymbolAddress(&csrc, g_tbl);
    cudaMemcpyAsync(cdst, csrc, sizeof(float) * BN * CNUM * 128,
                    cudaMemcpyDeviceToDevice);

    k_minmax<<<BN * 8, 256>>>((const float4*)x);
    k_build<<<NTILE, 256>>>((const float4*)x, lbl);
    const int ringBlocks = (BN * RINGN + 255) / 256;  // 128
    for (int c = 0; c < CNUM; c++) {
        k_fused<<<FTILE, 256>>>(c, c & 1);
        k_ring<<<ringBlocks, 256>>>(c, c & 1, lbl, index, w1, b1, w2, b2);
    }
    k_final<<<NPIX / 1024, 256>>>((float4*)d_out);
}